// round 2
// baseline (speedup 1.0000x reference)
#include <cuda_runtime.h>

// SO3Conv: x(1024,64,455) f32, D(64,455) f32, w(64,64,64) f32 -> out(1024,64,455) f32
//
// Stage 1: W2_l[k=f*d+u][j=g*d+v] = scale_l * sum_n D[n, off_l + u*d + v] * w[f,g,n]
//          scale_l = (1/sqrt(64)) * (1/sqrt(64*d)) = 0.125 / sqrt(64*d)
// Stage 2 (per l): y[b][j][m] = sum_k W2_l[k][j] * X[b][k][m]
//          X[b][k][m] = x[b, f, off_l + u*d + m]   (contiguous d-vector in m)
//          out index  = out[b, g, off_l + v*d + m] (contiguous d-vector in m)

#define BATCH 1024
#define FEAT  64
#define IRREP 455
#define NROT  64

// scratch: sum_l (64 d)^2 = 4096 * 455 floats = 7.45 MB
__device__ float g_W2[4096 * IRREP];

__constant__ int c_off[7] = {0, 1, 10, 35, 84, 165, 286};
__constant__ int c_d[7]   = {1, 3, 5, 7, 9, 11, 13};

// ---------------------------------------------------------------------------
// Stage 1: psi GEMM (M=4096 fg, K=64 n, N=455 i) + scatter into g_W2
// ---------------------------------------------------------------------------
__global__ void __launch_bounds__(256) prep_kernel(const float* __restrict__ Dm,
                                                   const float* __restrict__ w) {
    __shared__ float Wsh[64][65];  // w[fg, n] tile
    __shared__ float Dsh[64][65];  // D[n, i] tile

    const int tid = threadIdx.x;
    const int tx = tid & 15;       // i direction
    const int ty = tid >> 4;       // fg direction
    const int i0  = blockIdx.x * 64;
    const int fg0 = blockIdx.y * 64;

    // load w tile: rows fg0..fg0+63, all 64 n (contiguous)
    for (int t = tid; t < 64 * 64; t += 256) {
        int r = t >> 6, n = t & 63;
        Wsh[r][n] = w[(fg0 + r) * 64 + n];
    }
    // load D tile: rows n 0..63, cols i0..i0+63 (guarded)
    for (int t = tid; t < 64 * 64; t += 256) {
        int n = t >> 6, ii = t & 63;
        int i = i0 + ii;
        Dsh[n][ii] = (i < IRREP) ? Dm[n * IRREP + i] : 0.0f;
    }
    __syncthreads();

    float acc[4][4];
#pragma unroll
    for (int a = 0; a < 4; a++)
#pragma unroll
        for (int b = 0; b < 4; b++) acc[a][b] = 0.0f;

#pragma unroll 8
    for (int n = 0; n < 64; n++) {
        float wa[4], db[4];
#pragma unroll
        for (int a = 0; a < 4; a++) wa[a] = Wsh[ty + 16 * a][n];
#pragma unroll
        for (int b = 0; b < 4; b++) db[b] = Dsh[n][tx + 16 * b];
#pragma unroll
        for (int a = 0; a < 4; a++)
#pragma unroll
            for (int b = 0; b < 4; b++) acc[a][b] += wa[a] * db[b];
    }

    // scatter
#pragma unroll
    for (int a = 0; a < 4; a++) {
        int fg = fg0 + ty + 16 * a;
        int f = fg >> 6, g = fg & 63;
#pragma unroll
        for (int b = 0; b < 4; b++) {
            int i = i0 + tx + 16 * b;
            if (i >= IRREP) continue;
            // find l
            int l = 6;
#pragma unroll
            for (int q = 6; q >= 1; q--)
                if (i < c_off[q]) l = q - 1;
            int d = c_d[l], off = c_off[l];
            int r = i - off;
            int u = r / d, v = r - u * d;
            float scale = 0.125f / sqrtf(64.0f * (float)d);
            // base for l-block, [k][j] with k=f*d+u, j=g*d+v, row length 64*d
            g_W2[4096 * off + (f * d + u) * (64 * d) + (g * d + v)] = acc[a][b] * scale;
        }
    }
}

// ---------------------------------------------------------------------------
// Stage 2: per-l vectorized GEMM. Block tile: 32 b x 32 j, BK=16.
// Thread tile: 2 b x 2 j x D m (register accumulators).
// ---------------------------------------------------------------------------
template <int D>
__global__ void __launch_bounds__(256, 2) conv_kernel(const float* __restrict__ x,
                                                      float* __restrict__ out,
                                                      int off) {
    constexpr int K = 64 * D;
    constexpr int N = 64 * D;
    constexpr int BM = 32, BN = 32, BK = 16;
    constexpr int XROW = BK * D + 1;  // odd -> conflict-free row stride

    __shared__ float Xs[BM][XROW];    // [bi][ki*D + m]
    __shared__ float Ws[BK][BN];

    const float* __restrict__ W2l = g_W2 + 4096 * off;

    const int tid = threadIdx.x;
    const int tx = tid & 15;   // j direction
    const int ty = tid >> 4;   // b direction
    const int j0 = blockIdx.x * BN;
    const int b0 = blockIdx.y * BM;

    float acc[2][2][D];
#pragma unroll
    for (int a = 0; a < 2; a++)
#pragma unroll
        for (int c = 0; c < 2; c++)
#pragma unroll
            for (int m = 0; m < D; m++) acc[a][c][m] = 0.0f;

    for (int k0 = 0; k0 < K; k0 += BK) {
        // ---- load X tile: BM * BK * D floats (mostly contiguous gmem) ----
#pragma unroll 4
        for (int t = tid; t < BM * BK * D; t += 256) {
            int bi = t / (BK * D);
            int r  = t - bi * (BK * D);       // r = ki*D + m
            int ki = r / D;
            int m  = r - ki * D;
            int k  = k0 + ki;
            int f  = k / D;
            int u  = k - f * D;
            Xs[bi][r] = x[((b0 + bi) * FEAT + f) * IRREP + off + u * D + m];
        }
        // ---- load W tile: BK x BN, coalesced rows ----
#pragma unroll
        for (int t = tid; t < BK * BN; t += 256) {
            int ki = t >> 5, ji = t & 31;
            Ws[ki][ji] = W2l[(k0 + ki) * N + j0 + ji];
        }
        __syncthreads();

#pragma unroll 4
        for (int kk = 0; kk < BK; kk++) {
            float w0 = Ws[kk][tx];
            float w1 = Ws[kk][tx + 16];
            const float* xr0 = &Xs[ty][kk * D];
            const float* xr1 = &Xs[ty + 16][kk * D];
#pragma unroll
            for (int m = 0; m < D; m++) {
                float xa = xr0[m];
                float xb = xr1[m];
                acc[0][0][m] += xa * w0;
                acc[0][1][m] += xa * w1;
                acc[1][0][m] += xb * w0;
                acc[1][1][m] += xb * w1;
            }
        }
        __syncthreads();
    }

    // ---- store: each (b, j) gives a contiguous d-vector ----
#pragma unroll
    for (int a = 0; a < 2; a++) {
        int b = b0 + ty + a * 16;
#pragma unroll
        for (int c = 0; c < 2; c++) {
            int j = j0 + tx + c * 16;
            int g = j / D;
            int v = j - g * D;
            float* o = out + (b * FEAT + g) * IRREP + off + v * D;
#pragma unroll
            for (int m = 0; m < D; m++) o[m] = acc[a][c][m];
        }
    }
}

// ---------------------------------------------------------------------------
extern "C" void kernel_launch(void* const* d_in, const int* in_sizes, int n_in,
                              void* d_out, int out_size) {
    const float* x  = (const float*)d_in[0];
    const float* Dm = (const float*)d_in[1];
    const float* w  = (const float*)d_in[2];
    float* out = (float*)d_out;

    // Stage 1: grid (ceil(455/64)=8 i-tiles, 4096/64=64 fg-tiles)
    prep_kernel<<<dim3(8, 64), 256>>>(Dm, w);

    // Stage 2: one launch per l. grid = (N/32, 1024/32)
    conv_kernel<1> <<<dim3(64  / 32, 32), 256>>>(x, out, 0);
    conv_kernel<3> <<<dim3(192 / 32, 32), 256>>>(x, out, 1);
    conv_kernel<5> <<<dim3(320 / 32, 32), 256>>>(x, out, 10);
    conv_kernel<7> <<<dim3(448 / 32, 32), 256>>>(x, out, 35);
    conv_kernel<9> <<<dim3(576 / 32, 32), 256>>>(x, out, 84);
    conv_kernel<11><<<dim3(704 / 32, 32), 256>>>(x, out, 165);
    conv_kernel<13><<<dim3(832 / 32, 32), 256>>>(x, out, 286);
}

// round 3
// speedup vs baseline: 2.7589x; 2.7589x over previous
#include <cuda_runtime.h>

// SO3Conv: x(1024,64,455) f32, D(64,455) f32, w(64,64,64) f32 -> out(1024,64,455) f32
//
// Stage 1: W2_l[k=f*d+u][j=g*d+v] = scale_l * sum_n D[n, off_l + u*d + v] * w[f,g,n]
// Stage 2 (per l), flattened-m GEMM:
//   Y[(b,m)][j] = sum_k X[(b,m)][k] * W2_l[k][j]
//   X[(b,m)][k] = x[b, f, off + u*D + m],  k = f*D+u
//   out[b, g, off + v*D + m] = Y[(b,m)][g*D+v]

#define IRREP 455
typedef unsigned long long u64;

// scratch: sum_l (64 d)^2 = 4096 * 455 floats = 7.45 MB
__device__ float g_W2[4096 * IRREP];

__constant__ int c_off[7] = {0, 1, 10, 35, 84, 165, 286};
__constant__ int c_d[7]   = {1, 3, 5, 7, 9, 11, 13};

// ---------------------------------------------------------------------------
// f32x2 helpers (Blackwell packed FP32)
// ---------------------------------------------------------------------------
__device__ __forceinline__ void fma2(u64& d, u64 a, u64 b) {
    asm("fma.rn.f32x2 %0, %1, %2, %0;" : "+l"(d) : "l"(a), "l"(b));
}
__device__ __forceinline__ u64 bcast2(float v) {
    u64 r;
    unsigned u = __float_as_uint(v);
    asm("mov.b64 %0, {%1, %1};" : "=l"(r) : "r"(u));
    return r;
}
__device__ __forceinline__ float lo32(u64 a) { return __uint_as_float((unsigned)a); }
__device__ __forceinline__ float hi32(u64 a) { return __uint_as_float((unsigned)(a >> 32)); }

// ---------------------------------------------------------------------------
// Stage 1: psi GEMM (M=4096 fg, K=64 n, N=455 i) + scatter into g_W2
// ---------------------------------------------------------------------------
__global__ void __launch_bounds__(256) prep_kernel(const float* __restrict__ Dm,
                                                   const float* __restrict__ w) {
    __shared__ float Wsh[64][65];
    __shared__ float Dsh[64][65];

    const int tid = threadIdx.x;
    const int tx = tid & 15;
    const int ty = tid >> 4;
    const int i0  = blockIdx.x * 64;
    const int fg0 = blockIdx.y * 64;

    for (int t = tid; t < 64 * 64; t += 256) {
        int r = t >> 6, n = t & 63;
        Wsh[r][n] = w[(fg0 + r) * 64 + n];
    }
    for (int t = tid; t < 64 * 64; t += 256) {
        int n = t >> 6, ii = t & 63;
        int i = i0 + ii;
        Dsh[n][ii] = (i < IRREP) ? Dm[n * IRREP + i] : 0.0f;
    }
    __syncthreads();

    float acc[4][4];
#pragma unroll
    for (int a = 0; a < 4; a++)
#pragma unroll
        for (int b = 0; b < 4; b++) acc[a][b] = 0.0f;

#pragma unroll 8
    for (int n = 0; n < 64; n++) {
        float wa[4], db[4];
#pragma unroll
        for (int a = 0; a < 4; a++) wa[a] = Wsh[ty + 16 * a][n];
#pragma unroll
        for (int b = 0; b < 4; b++) db[b] = Dsh[n][tx + 16 * b];
#pragma unroll
        for (int a = 0; a < 4; a++)
#pragma unroll
            for (int b = 0; b < 4; b++) acc[a][b] += wa[a] * db[b];
    }

#pragma unroll
    for (int a = 0; a < 4; a++) {
        int fg = fg0 + ty + 16 * a;
        int f = fg >> 6, g = fg & 63;
#pragma unroll
        for (int b = 0; b < 4; b++) {
            int i = i0 + tx + 16 * b;
            if (i >= IRREP) continue;
            int l = 6;
#pragma unroll
            for (int q = 6; q >= 1; q--)
                if (i < c_off[q]) l = q - 1;
            int d = c_d[l], off = c_off[l];
            int r = i - off;
            int u = r / d, v = r - u * d;
            float scale = 0.125f / sqrtf(64.0f * (float)d);
            g_W2[4096 * off + (f * d + u) * (64 * d) + (g * d + v)] = acc[a][b] * scale;
        }
    }
}

// ---------------------------------------------------------------------------
// Stage 2 body: flat GEMM tile. BM=128 (bm rows), BN=64 (j cols), BK=16.
// 256 threads, thread tile 8bm x 4j, f32x2 packed over bm pairs.
// ---------------------------------------------------------------------------
template <int D>
__device__ __forceinline__ void conv_body(const float* __restrict__ x,
                                          float* __restrict__ out,
                                          int off, int rel, float* sm) {
    constexpr int K = 64 * D;
    constexpr int N = 64 * D;

    float (*Xs)[128] = (float (*)[128])sm;           // [16][128]
    float (*Ws)[64]  = (float (*)[64])(sm + 16 * 128); // [16][64]

    const int tid = threadIdx.x;
    const int tx = tid & 15;    // j group  (4 cols each)
    const int ty = tid >> 4;    // bm group (8 rows each)

    const int bm_tiles = 8 * D;
    const int jt = rel / bm_tiles;
    const int bt = rel - jt * bm_tiles;
    const int r0 = bt * 128;
    const int j0 = jt * 64;

    const float* __restrict__ W2l = g_W2 + 4096 * off;

    // --- X loader: each thread loads 8 elems: bm = tid&127, kk = (tid>>7)+2i
    const int lbm = tid & 127;
    const int lk0 = tid >> 7;                 // 0 or 1
    const int lr  = r0 + lbm;
    const int lb  = lr / D;
    const int lm  = lr - lb * D;
    const float* __restrict__ xbm = x + (lb * 64) * IRREP + off + lm;

    // --- W loader: each thread loads 4 elems: j = tid&63, kk = (tid>>6)+4i
    const int wj  = tid & 63;
    const int wk0 = tid >> 6;                 // 0..3

    u64 acc[4][4];
#pragma unroll
    for (int a = 0; a < 4; a++)
#pragma unroll
        for (int b = 0; b < 4; b++) acc[a][b] = 0ull;

    float xr[8], wr[4];
    // prefetch tile k0 = 0
#pragma unroll
    for (int i = 0; i < 8; i++) {
        int k = lk0 + 2 * i;
        int f = k / D, u = k - f * D;
        xr[i] = xbm[f * IRREP + u * D];
    }
#pragma unroll
    for (int i = 0; i < 4; i++)
        wr[i] = W2l[(wk0 + 4 * i) * N + j0 + wj];

    for (int k0 = 0; k0 < K; k0 += 16) {
        // stage to smem
#pragma unroll
        for (int i = 0; i < 8; i++) Xs[lk0 + 2 * i][lbm] = xr[i];
#pragma unroll
        for (int i = 0; i < 4; i++) Ws[wk0 + 4 * i][wj] = wr[i];
        __syncthreads();

        // prefetch next tile (overlaps with compute below)
        if (k0 + 16 < K) {
#pragma unroll
            for (int i = 0; i < 8; i++) {
                int k = k0 + 16 + lk0 + 2 * i;
                int f = k / D, u = k - f * D;
                xr[i] = xbm[f * IRREP + u * D];
            }
#pragma unroll
            for (int i = 0; i < 4; i++)
                wr[i] = W2l[(k0 + 16 + wk0 + 4 * i) * N + j0 + wj];
        }

#pragma unroll
        for (int kk = 0; kk < 16; kk++) {
            ulonglong2 xa = *(const ulonglong2*)&Xs[kk][ty * 8];
            ulonglong2 xb = *(const ulonglong2*)&Xs[kk][ty * 8 + 4];
            float4 wv = *(const float4*)&Ws[kk][tx * 4];
            u64 w0 = bcast2(wv.x), w1 = bcast2(wv.y);
            u64 w2 = bcast2(wv.z), w3 = bcast2(wv.w);
            fma2(acc[0][0], xa.x, w0); fma2(acc[0][1], xa.x, w1);
            fma2(acc[0][2], xa.x, w2); fma2(acc[0][3], xa.x, w3);
            fma2(acc[1][0], xa.y, w0); fma2(acc[1][1], xa.y, w1);
            fma2(acc[1][2], xa.y, w2); fma2(acc[1][3], xa.y, w3);
            fma2(acc[2][0], xb.x, w0); fma2(acc[2][1], xb.x, w1);
            fma2(acc[2][2], xb.x, w2); fma2(acc[2][3], xb.x, w3);
            fma2(acc[3][0], xb.y, w0); fma2(acc[3][1], xb.y, w1);
            fma2(acc[3][2], xb.y, w2); fma2(acc[3][3], xb.y, w3);
        }
        __syncthreads();
    }

    // --- store: row r -> (b,m), col jj -> (g,v)
#pragma unroll
    for (int bp = 0; bp < 4; bp++) {
        int rA = r0 + ty * 8 + 2 * bp;
        int bA = rA / D, mA = rA - bA * D;
        int rB = rA + 1;
        int bB = rB / D, mB = rB - bB * D;
#pragma unroll
        for (int jc = 0; jc < 4; jc++) {
            int jj = j0 + tx * 4 + jc;
            int g = jj / D, v = jj - g * D;
            int col = off + v * D;
            out[(bA * 64 + g) * IRREP + col + mA] = lo32(acc[bp][jc]);
            out[(bB * 64 + g) * IRREP + col + mB] = hi32(acc[bp][jc]);
        }
    }
}

// ---------------------------------------------------------------------------
// Fused dispatcher: blocks ordered descending D to avoid wave tails.
// blocks per l = 8*D*D: 1352,968,648,392,200,72,8 (cum: 1352,2320,2968,3360,3560,3632,3640)
// ---------------------------------------------------------------------------
__global__ void __launch_bounds__(256, 3) conv_fused(const float* __restrict__ x,
                                                     float* __restrict__ out) {
    __shared__ __align__(16) float sm[16 * 128 + 16 * 64];
    const int bid = blockIdx.x;
    if (bid < 1352)      conv_body<13>(x, out, 286, bid,        sm);
    else if (bid < 2320) conv_body<11>(x, out, 165, bid - 1352, sm);
    else if (bid < 2968) conv_body<9> (x, out, 84,  bid - 2320, sm);
    else if (bid < 3360) conv_body<7> (x, out, 35,  bid - 2968, sm);
    else if (bid < 3560) conv_body<5> (x, out, 10,  bid - 3360, sm);
    else if (bid < 3632) conv_body<3> (x, out, 1,   bid - 3560, sm);
    else                 conv_body<1> (x, out, 0,   bid - 3632, sm);
}

// ---------------------------------------------------------------------------
extern "C" void kernel_launch(void* const* d_in, const int* in_sizes, int n_in,
                              void* d_out, int out_size) {
    const float* x  = (const float*)d_in[0];
    const float* Dm = (const float*)d_in[1];
    const float* w  = (const float*)d_in[2];
    float* out = (float*)d_out;

    prep_kernel<<<dim3(8, 64), 256>>>(Dm, w);
    conv_fused<<<3640, 256>>>(x, out);
}

// round 7
// speedup vs baseline: 5.4659x; 1.9812x over previous
#include <cuda_runtime.h>
#include <cuda_bf16.h>
#include <cstdint>

// SO3Conv via bf16-split HMMA (mma.sync) GEMM — compute_103-safe (no tcgen05).
// Stage A (prep):   W2T_l[j=g*d+v][k=f*d+u] = scale_l * psi, split to bf16 hi/lo
// Stage B (repack): X_l[r=b*d+m][k=f*d+u]   = x[b,f,off+u*d+m], split to bf16 hi/lo
// Stage C (gemm):   Y[r][j] = sum_k X[r][k]*W2T[j][k], 3-term split hh+hl+lh,
//                   fp32 accum in registers, scatter via LUT.

#define IRREP 455

__device__ __align__(16) __nv_bfloat16 g_Xh[29818880];   // 65536*455
__device__ __align__(16) __nv_bfloat16 g_Xl[29818880];
__device__ __align__(16) __nv_bfloat16 g_Wh[1863680];    // 4096*455
__device__ __align__(16) __nv_bfloat16 g_Wl[1863680];
__device__ int g_lut[3136];                              // 64 * sum(d)

__constant__ int c_off[7] = {0, 1, 10, 35, 84, 165, 286};
__constant__ int c_d[7]   = {1, 3, 5, 7, 9, 11, 13};
__constant__ int c_jb[7]  = {0, 64, 256, 576, 1024, 1600, 2304};

// gemm tile tables, DESCENDING d (q=0..6 -> l=6..0). blocks per l = 8*d*d.
__constant__ int P_CUM[8] = {0, 1352, 2320, 2968, 3360, 3560, 3632, 3640};
__constant__ int P_D[7]   = {13, 11, 9, 7, 5, 3, 1};
__constant__ int P_OFF[7] = {286, 165, 84, 35, 10, 1, 0};
__constant__ int P_JB[7]  = {2304, 1600, 1024, 576, 256, 64, 0};

// ---------------------------------------------------------------------------
// PTX helpers (all baseline compute_103-legal)
// ---------------------------------------------------------------------------
__device__ __forceinline__ uint32_t smem_u32(const void* p) {
    uint32_t a;
    asm("{ .reg .u64 t; cvta.to.shared.u64 t, %1; cvt.u32.u64 %0, t; }" : "=r"(a) : "l"(p));
    return a;
}
__device__ __forceinline__ void cpasync16(uint32_t s, const void* g) {
    asm volatile("cp.async.cg.shared.global [%0], [%1], 16;" :: "r"(s), "l"(g));
}
#define CP_COMMIT() asm volatile("cp.async.commit_group;" ::: "memory")
#define CP_WAIT0()  asm volatile("cp.async.wait_group 0;" ::: "memory")

__device__ __forceinline__ void ldsm_x4(uint32_t* r, uint32_t addr) {
    asm volatile("ldmatrix.sync.aligned.m8n8.x4.shared.b16 {%0,%1,%2,%3}, [%4];"
        : "=r"(r[0]), "=r"(r[1]), "=r"(r[2]), "=r"(r[3]) : "r"(addr));
}
__device__ __forceinline__ void mma16816(float* c, const uint32_t* a, const uint32_t* b) {
    asm volatile("mma.sync.aligned.m16n8k16.row.col.f32.bf16.bf16.f32 "
        "{%0,%1,%2,%3}, {%4,%5,%6,%7}, {%8,%9}, {%0,%1,%2,%3};"
        : "+f"(c[0]), "+f"(c[1]), "+f"(c[2]), "+f"(c[3])
        : "r"(a[0]), "r"(a[1]), "r"(a[2]), "r"(a[3]), "r"(b[0]), "r"(b[1]));
}

// ---------------------------------------------------------------------------
// Stage A: psi GEMM (M=4096 fg, K=64 n, N=455 i) -> W2T bf16 hi/lo
// ---------------------------------------------------------------------------
__global__ void __launch_bounds__(256) prep_kernel(const float* __restrict__ Dm,
                                                   const float* __restrict__ w) {
    __shared__ float Wsh[64][65];
    __shared__ float Dsh[64][65];

    const int tid = threadIdx.x;
    const int tx = tid & 15;
    const int ty = tid >> 4;
    const int i0  = blockIdx.x * 64;
    const int fg0 = blockIdx.y * 64;

    for (int t = tid; t < 64 * 64; t += 256) {
        int r = t >> 6, n = t & 63;
        Wsh[r][n] = w[(fg0 + r) * 64 + n];
    }
    for (int t = tid; t < 64 * 64; t += 256) {
        int n = t >> 6, ii = t & 63;
        int i = i0 + ii;
        Dsh[n][ii] = (i < IRREP) ? Dm[n * IRREP + i] : 0.0f;
    }
    __syncthreads();

    float acc[4][4];
#pragma unroll
    for (int a = 0; a < 4; a++)
#pragma unroll
        for (int b = 0; b < 4; b++) acc[a][b] = 0.0f;

#pragma unroll 8
    for (int n = 0; n < 64; n++) {
        float wa[4], db[4];
#pragma unroll
        for (int a = 0; a < 4; a++) wa[a] = Wsh[ty + 16 * a][n];
#pragma unroll
        for (int b = 0; b < 4; b++) db[b] = Dsh[n][tx + 16 * b];
#pragma unroll
        for (int a = 0; a < 4; a++)
#pragma unroll
            for (int b = 0; b < 4; b++) acc[a][b] += wa[a] * db[b];
    }

#pragma unroll
    for (int a = 0; a < 4; a++) {
        int fg = fg0 + ty + 16 * a;
        int f = fg >> 6, g = fg & 63;
#pragma unroll
        for (int b = 0; b < 4; b++) {
            int i = i0 + tx + 16 * b;
            if (i >= IRREP) continue;
            int l = 6;
#pragma unroll
            for (int q = 6; q >= 1; q--)
                if (i < c_off[q]) l = q - 1;
            int d = c_d[l], off = c_off[l];
            int r = i - off;
            int u = r / d, v = r - u * d;
            float scale = 0.125f / sqrtf(64.0f * (float)d);
            float val = acc[a][b] * scale;
            __nv_bfloat16 h = __float2bfloat16(val);
            __nv_bfloat16 lo = __float2bfloat16(val - __bfloat162float(h));
            long idx = 4096L * off + (long)(g * d + v) * (64 * d) + (f * d + u);
            g_Wh[idx] = h;
            g_Wl[idx] = lo;
        }
    }
}

// ---------------------------------------------------------------------------
// Stage B: repack x -> X (bf16 hi/lo), one CTA per (b, l)
// ---------------------------------------------------------------------------
__global__ void __launch_bounds__(256) repack_kernel(const float* __restrict__ x) {
    __shared__ float xs[64 * 169];
    __shared__ short f_of[832], u_of[832];

    const int tid = threadIdx.x;
    const int b = blockIdx.x;
    const int l = blockIdx.y;
    const int d = c_d[l], off = c_off[l];
    const int d2 = d * d, Kl = 64 * d;

    for (int t = tid; t < 64 * d2; t += 256) {
        int f = t / d2, s = t - f * d2;
        xs[t] = x[((b << 6) + f) * IRREP + off + s];
    }
    for (int k = tid; k < Kl; k += 256) {
        int f = k / d;
        f_of[k] = (short)f;
        u_of[k] = (short)(k - f * d);
    }
    __syncthreads();

    const long Xbase = 65536L * off;
    for (int t = tid; t < 64 * d2; t += 256) {
        int m = t / Kl;
        int k = t - m * Kl;
        float val = xs[(int)f_of[k] * d2 + (int)u_of[k] * d + m];
        __nv_bfloat16 h = __float2bfloat16(val);
        __nv_bfloat16 lo = __float2bfloat16(val - __bfloat162float(h));
        long idx = Xbase + (long)(b * d + m) * Kl + k;
        g_Xh[idx] = h;
        g_Xl[idx] = lo;
    }
}

__global__ void lut_kernel() {
    int l = blockIdx.x;
    int d = c_d[l], off = c_off[l], jb = c_jb[l];
    for (int t = threadIdx.x; t < 64 * d; t += 256) {
        int g = t / d, v = t - g * d;
        g_lut[jb + t] = g * IRREP + v * d + off;
    }
}

// ---------------------------------------------------------------------------
// Stage C: HMMA GEMM. CTA = 128 rows x 64 cols, 4 warps (each 64x32),
// K chunks of 32, cp.async double buffer, 3-term bf16 split.
// smem per stage: Ah 128x(32bf16,stride 80B)=10240, Al 10240, Bh 5120, Bl 5120
// ---------------------------------------------------------------------------
#define ST      30720
#define OFF_AH  0
#define OFF_AL  10240
#define OFF_BH  20480
#define OFF_BL  25600
#define SM_TOT  (2 * ST)   // 61440

__global__ void __launch_bounds__(128) gemm_kernel(float* __restrict__ out) {
    extern __shared__ __align__(16) char smem[];
    const uint32_t sbase = smem_u32(smem);
    __shared__ int lutS[64];

    const int tid = threadIdx.x;
    const int lane = tid & 31;
    const int wid = tid >> 5;
    const int wm = wid >> 1;        // 0..1 : m half
    const int wn = wid & 1;         // 0..1 : n half

    // locate tile
    const int bid = blockIdx.x;
    int q = 0;
#pragma unroll
    for (int t = 1; t < 7; t++)
        if (bid >= P_CUM[t]) q = t;
    const int rel = bid - P_CUM[q];
    const int d  = P_D[q];
    const int Kl = 64 * d;
    const int bt = rel / d;
    const int jt = rel - bt * d;
    const int R0 = bt * 128;
    const int j0 = jt * 64;
    const int nc = 2 * d;

    const __nv_bfloat16* __restrict__ Xh = g_Xh + 65536L * P_OFF[q];
    const __nv_bfloat16* __restrict__ Xl = g_Xl + 65536L * P_OFF[q];
    const __nv_bfloat16* __restrict__ Wh = g_Wh + 4096L * P_OFF[q];
    const __nv_bfloat16* __restrict__ Wl = g_Wl + 4096L * P_OFF[q];

    if (tid < 64) lutS[tid] = g_lut[P_JB[q] + j0 + tid];

    // ldmatrix per-thread addresses (byte offsets within a plane)
    uint32_t addrA[4], addrB[2];
#pragma unroll
    for (int mf = 0; mf < 4; mf++)
        addrA[mf] = (uint32_t)((wm * 64 + mf * 16 + (lane & 15)) * 80 + ((lane >> 4) & 1) * 16);
#pragma unroll
    for (int nn = 0; nn < 2; nn++)
        addrB[nn] = (uint32_t)((wn * 32 + nn * 16 + ((lane >> 3) & 2) * 4 + (lane & 7)) * 80
                               + ((lane >> 3) & 1) * 16);

    float acc[4][4][4];
#pragma unroll
    for (int mf = 0; mf < 4; mf++)
#pragma unroll
        for (int ns = 0; ns < 4; ns++)
#pragma unroll
            for (int i = 0; i < 4; i++) acc[mf][ns][i] = 0.0f;

    const int rr = tid >> 2;
    const int cc = tid & 3;

    // prefetch chunk 0 into stage 0
    {
        uint32_t sb = sbase;
#pragma unroll
        for (int i = 0; i < 4; i++) {
            int r = rr + 32 * i;
            long g = (long)(R0 + r) * Kl + cc * 8;
            cpasync16(sb + OFF_AH + r * 80 + cc * 16, Xh + g);
            cpasync16(sb + OFF_AL + r * 80 + cc * 16, Xl + g);
        }
#pragma unroll
        for (int i = 0; i < 2; i++) {
            int r = rr + 32 * i;
            long g = (long)(j0 + r) * Kl + cc * 8;
            cpasync16(sb + OFF_BH + r * 80 + cc * 16, Wh + g);
            cpasync16(sb + OFF_BL + r * 80 + cc * 16, Wl + g);
        }
        CP_COMMIT();
    }

    for (int c = 0; c < nc; c++) {
        CP_WAIT0();
        __syncthreads();   // chunk c visible; prior readers of other stage done

        if (c + 1 < nc) {  // async prefetch c+1 into other stage, overlaps compute
            uint32_t sb = sbase + (uint32_t)(((c + 1) & 1) * ST);
            int k0 = (c + 1) * 32;
#pragma unroll
            for (int i = 0; i < 4; i++) {
                int r = rr + 32 * i;
                long g = (long)(R0 + r) * Kl + k0 + cc * 8;
                cpasync16(sb + OFF_AH + r * 80 + cc * 16, Xh + g);
                cpasync16(sb + OFF_AL + r * 80 + cc * 16, Xl + g);
            }
#pragma unroll
            for (int i = 0; i < 2; i++) {
                int r = rr + 32 * i;
                long g = (long)(j0 + r) * Kl + k0 + cc * 8;
                cpasync16(sb + OFF_BH + r * 80 + cc * 16, Wh + g);
                cpasync16(sb + OFF_BL + r * 80 + cc * 16, Wl + g);
            }
            CP_COMMIT();
        }

        const uint32_t sb = sbase + (uint32_t)((c & 1) * ST);
#pragma unroll
        for (int ks = 0; ks < 2; ks++) {
            const uint32_t ko = (uint32_t)(ks * 32);
            uint32_t a[4][4], bh[2][4], bl[2][4];
#pragma unroll
            for (int mf = 0; mf < 4; mf++) ldsm_x4(a[mf], sb + OFF_AH + addrA[mf] + ko);
#pragma unroll
            for (int nn = 0; nn < 2; nn++) ldsm_x4(bh[nn], sb + OFF_BH + addrB[nn] + ko);
#pragma unroll
            for (int nn = 0; nn < 2; nn++) ldsm_x4(bl[nn], sb + OFF_BL + addrB[nn] + ko);

            // hh + hl
#pragma unroll
            for (int mf = 0; mf < 4; mf++)
#pragma unroll
                for (int ns = 0; ns < 4; ns++) {
                    mma16816(acc[mf][ns], a[mf], &bh[ns >> 1][(ns & 1) * 2]);
                    mma16816(acc[mf][ns], a[mf], &bl[ns >> 1][(ns & 1) * 2]);
                }
            // lh
#pragma unroll
            for (int mf = 0; mf < 4; mf++) ldsm_x4(a[mf], sb + OFF_AL + addrA[mf] + ko);
#pragma unroll
            for (int mf = 0; mf < 4; mf++)
#pragma unroll
                for (int ns = 0; ns < 4; ns++)
                    mma16816(acc[mf][ns], a[mf], &bh[ns >> 1][(ns & 1) * 2]);
        }
        __syncthreads();   // all warps done with stage c&1 before it is re-staged
    }

    // ---- epilogue: scatter via LUT ----
#pragma unroll
    for (int mf = 0; mf < 4; mf++) {
        int row0 = R0 + wm * 64 + mf * 16 + (lane >> 2);
        int row1 = row0 + 8;
        int b0 = row0 / d, m0 = row0 - b0 * d;
        int b1 = row1 / d, m1 = row1 - b1 * d;
        long ob0 = (long)b0 * 29120 + m0;
        long ob1 = (long)b1 * 29120 + m1;
#pragma unroll
        for (int ns = 0; ns < 4; ns++) {
            int j = wn * 32 + ns * 8 + (lane & 3) * 2;
            int o0 = lutS[j], o1 = lutS[j + 1];
            out[ob0 + o0] = acc[mf][ns][0];
            out[ob0 + o1] = acc[mf][ns][1];
            out[ob1 + o0] = acc[mf][ns][2];
            out[ob1 + o1] = acc[mf][ns][3];
        }
    }
}

// ---------------------------------------------------------------------------
extern "C" void kernel_launch(void* const* d_in, const int* in_sizes, int n_in,
                              void* d_out, int out_size) {
    const float* x  = (const float*)d_in[0];
    const float* Dm = (const float*)d_in[1];
    const float* w  = (const float*)d_in[2];
    float* out = (float*)d_out;

    cudaFuncSetAttribute(gemm_kernel, cudaFuncAttributeMaxDynamicSharedMemorySize, SM_TOT);

    prep_kernel<<<dim3(8, 64), 256>>>(Dm, w);
    repack_kernel<<<dim3(1024, 7), 256>>>(x);
    lut_kernel<<<7, 256>>>();
    gemm_kernel<<<3640, 128, SM_TOT>>>(out);
}

// round 8
// speedup vs baseline: 6.9902x; 1.2789x over previous
#include <cuda_runtime.h>
#include <cuda_bf16.h>
#include <cstdint>

// SO3Conv via bf16-split HMMA (mma.sync) GEMM — compute_103-safe.
// prepare (fused):  prep -> W2T bf16 hi/lo, repack -> X bf16 hi/lo, lut
// gemm:             Y[r][j] = sum_k X[r][k]*W2T[j][k], hh+hl+lh split,
//                   fp32 accum, XOR-swizzled smem, 4 CTAs/SM.

#define IRREP 455

__device__ __align__(16) __nv_bfloat16 g_Xh[29818880];   // 65536*455
__device__ __align__(16) __nv_bfloat16 g_Xl[29818880];
__device__ __align__(16) __nv_bfloat16 g_Wh[1863680];    // 4096*455
__device__ __align__(16) __nv_bfloat16 g_Wl[1863680];
__device__ int g_lut[3136];                              // 64 * sum(d)

__constant__ int c_off[7] = {0, 1, 10, 35, 84, 165, 286};
__constant__ int c_d[7]   = {1, 3, 5, 7, 9, 11, 13};
__constant__ int c_jb[7]  = {0, 64, 256, 576, 1024, 1600, 2304};

// gemm tile tables, DESCENDING d (q=0..6 -> l=6..0). blocks per l = 8*d*d.
__constant__ int P_CUM[8] = {0, 1352, 2320, 2968, 3360, 3560, 3632, 3640};
__constant__ int P_D[7]   = {13, 11, 9, 7, 5, 3, 1};
__constant__ int P_OFF[7] = {286, 165, 84, 35, 10, 1, 0};
__constant__ int P_JB[7]  = {2304, 1600, 1024, 576, 256, 64, 0};

// ---------------------------------------------------------------------------
// PTX helpers
// ---------------------------------------------------------------------------
__device__ __forceinline__ uint32_t smem_u32(const void* p) {
    uint32_t a;
    asm("{ .reg .u64 t; cvta.to.shared.u64 t, %1; cvt.u32.u64 %0, t; }" : "=r"(a) : "l"(p));
    return a;
}
__device__ __forceinline__ void cpasync16(uint32_t s, const void* g) {
    asm volatile("cp.async.cg.shared.global [%0], [%1], 16;" :: "r"(s), "l"(g));
}
#define CP_COMMIT() asm volatile("cp.async.commit_group;" ::: "memory")
#define CP_WAIT0()  asm volatile("cp.async.wait_group 0;" ::: "memory")

__device__ __forceinline__ void ldsm_x4(uint32_t* r, uint32_t addr) {
    asm volatile("ldmatrix.sync.aligned.m8n8.x4.shared.b16 {%0,%1,%2,%3}, [%4];"
        : "=r"(r[0]), "=r"(r[1]), "=r"(r[2]), "=r"(r[3]) : "r"(addr));
}
__device__ __forceinline__ void mma16816(float* c, const uint32_t* a, const uint32_t* b) {
    asm volatile("mma.sync.aligned.m16n8k16.row.col.f32.bf16.bf16.f32 "
        "{%0,%1,%2,%3}, {%4,%5,%6,%7}, {%8,%9}, {%0,%1,%2,%3};"
        : "+f"(c[0]), "+f"(c[1]), "+f"(c[2]), "+f"(c[3])
        : "r"(a[0]), "r"(a[1]), "r"(a[2]), "r"(a[3]), "r"(b[0]), "r"(b[1]));
}

// smem XOR swizzle: row stride 64B, 16B chunk c -> c ^ ((row>>1)&3)
__device__ __forceinline__ uint32_t swz(int row, int c) {
    return (uint32_t)(row * 64 + ((c ^ ((row >> 1) & 3)) << 4));
}
__device__ __forceinline__ uint32_t pack_bf2(__nv_bfloat16 a, __nv_bfloat16 b) {
    return (uint32_t)__bfloat16_as_ushort(a) | ((uint32_t)__bfloat16_as_ushort(b) << 16);
}

// ---------------------------------------------------------------------------
// Fused prepare kernel: [0,512) prep | [512,7680) repack | [7680,7687) lut
// ---------------------------------------------------------------------------
__global__ void __launch_bounds__(256) prepare_kernel(const float* __restrict__ x,
                                                      const float* __restrict__ Dm,
                                                      const float* __restrict__ w) {
    extern __shared__ __align__(16) char sm[];
    const int tid = threadIdx.x;
    const int bid = blockIdx.x;

    if (bid < 512) {
        // ---- prep: psi GEMM (4096 fg x 455 i, K=64) -> W2T bf16 hi/lo ----
        float (*Wsh)[65] = (float (*)[65])sm;
        float (*Dsh)[65] = (float (*)[65])(sm + 64 * 65 * 4);

        const int tx = tid & 15;
        const int ty = tid >> 4;
        const int i0  = (bid & 7) * 64;
        const int fg0 = (bid >> 3) * 64;

        for (int t = tid; t < 64 * 64; t += 256) {
            int r = t >> 6, n = t & 63;
            Wsh[r][n] = w[(fg0 + r) * 64 + n];
        }
        for (int t = tid; t < 64 * 64; t += 256) {
            int n = t >> 6, ii = t & 63;
            int i = i0 + ii;
            Dsh[n][ii] = (i < IRREP) ? Dm[n * IRREP + i] : 0.0f;
        }
        __syncthreads();

        float acc[4][4];
#pragma unroll
        for (int a = 0; a < 4; a++)
#pragma unroll
            for (int b = 0; b < 4; b++) acc[a][b] = 0.0f;

#pragma unroll 8
        for (int n = 0; n < 64; n++) {
            float wa[4], db[4];
#pragma unroll
            for (int a = 0; a < 4; a++) wa[a] = Wsh[ty + 16 * a][n];
#pragma unroll
            for (int b = 0; b < 4; b++) db[b] = Dsh[n][tx + 16 * b];
#pragma unroll
            for (int a = 0; a < 4; a++)
#pragma unroll
                for (int b = 0; b < 4; b++) acc[a][b] += wa[a] * db[b];
        }

#pragma unroll
        for (int a = 0; a < 4; a++) {
            int fg = fg0 + ty + 16 * a;
            int f = fg >> 6, g = fg & 63;
#pragma unroll
            for (int b = 0; b < 4; b++) {
                int i = i0 + tx + 16 * b;
                if (i >= IRREP) continue;
                int l = 6;
#pragma unroll
                for (int q = 6; q >= 1; q--)
                    if (i < c_off[q]) l = q - 1;
                int d = c_d[l], off = c_off[l];
                int r = i - off;
                int u = r / d, v = r - u * d;
                float scale = 0.125f / sqrtf(64.0f * (float)d);
                float val = acc[a][b] * scale;
                __nv_bfloat16 h = __float2bfloat16(val);
                __nv_bfloat16 lo = __float2bfloat16(val - __bfloat162float(h));
                long idx = 4096L * off + (long)(g * d + v) * (64 * d) + (f * d + u);
                g_Wh[idx] = h;
                g_Wl[idx] = lo;
            }
        }
    } else if (bid < 7680) {
        // ---- repack: X_l[r=b*d+m][k=f*d+u] = x[b,f,off+u*d+m], bf16 hi/lo ----
        float* xs   = (float*)sm;                 // up to 64*169 floats
        short* f_of = (short*)(sm + 43264);
        short* u_of = f_of + 832;

        const int rel = bid - 512;
        const int l = 6 - (rel >> 10);            // descending d
        const int b = rel & 1023;
        const int d = c_d[l], off = c_off[l];
        const int d2 = d * d, Kl = 64 * d;

        for (int t = tid; t < 64 * d2; t += 256) {
            int f = t / d2, s = t - f * d2;
            xs[t] = x[((b << 6) + f) * IRREP + off + s];
        }
        for (int k = tid; k < Kl; k += 256) {
            int f = k / d;
            f_of[k] = (short)f;
            u_of[k] = (short)(k - f * d);
        }
        __syncthreads();

        const long Xbase = 65536L * off;
        const int slots = 16 * d2;                // groups of 4 k
        for (int t = tid; t < slots; t += 256) {
            int m = t / (16 * d);
            int k = (t - m * (16 * d)) * 4;
            uint32_t H[2], L[2];
#pragma unroll
            for (int p = 0; p < 2; p++) {
                __nv_bfloat16 h0, h1, l0, l1;
                {
                    int ki = k + 2 * p;
                    float v = xs[(int)f_of[ki] * d2 + (int)u_of[ki] * d + m];
                    h0 = __float2bfloat16(v);
                    l0 = __float2bfloat16(v - __bfloat162float(h0));
                    ki++;
                    v = xs[(int)f_of[ki] * d2 + (int)u_of[ki] * d + m];
                    h1 = __float2bfloat16(v);
                    l1 = __float2bfloat16(v - __bfloat162float(h1));
                }
                H[p] = pack_bf2(h0, h1);
                L[p] = pack_bf2(l0, l1);
            }
            long idx = Xbase + (long)(b * d + m) * Kl + k;
            *(uint2*)(g_Xh + idx) = make_uint2(H[0], H[1]);
            *(uint2*)(g_Xl + idx) = make_uint2(L[0], L[1]);
        }
    } else {
        // ---- lut ----
        int l = bid - 7680;
        int d = c_d[l], off = c_off[l], jb = c_jb[l];
        for (int t = tid; t < 64 * d; t += 256) {
            int g = t / d, v = t - g * d;
            g_lut[jb + t] = g * IRREP + v * d + off;
        }
    }
}

// ---------------------------------------------------------------------------
// gemm: CTA = 128 rows x 64 cols, 4 warps (64x32 each), K chunks of 32,
// cp.async double buffer, XOR-swizzled smem (64B rows), 3-term bf16 split.
// per stage: Ah 8192 | Al 8192 | Bh 4096 | Bl 4096 = 24576; x2 = 49152.
// ---------------------------------------------------------------------------
#define ST      24576
#define OFF_AH  0
#define OFF_AL  8192
#define OFF_BH  16384
#define OFF_BL  20480
#define SM_TOT  (2 * ST)   // 49152

__global__ void __launch_bounds__(128, 4) gemm_kernel(float* __restrict__ out) {
    extern __shared__ __align__(16) char smem[];
    const uint32_t sbase = smem_u32(smem);
    __shared__ int lutS[64];

    const int tid = threadIdx.x;
    const int lane = tid & 31;
    const int wid = tid >> 5;
    const int wm = wid >> 1;
    const int wn = wid & 1;

    const int bid = blockIdx.x;
    int q = 0;
#pragma unroll
    for (int t = 1; t < 7; t++)
        if (bid >= P_CUM[t]) q = t;
    const int rel = bid - P_CUM[q];
    const int d  = P_D[q];
    const int Kl = 64 * d;
    const int bt = rel / d;
    const int jt = rel - bt * d;
    const int R0 = bt * 128;
    const int j0 = jt * 64;
    const int nc = 2 * d;

    const __nv_bfloat16* __restrict__ Xh = g_Xh + 65536L * P_OFF[q];
    const __nv_bfloat16* __restrict__ Xl = g_Xl + 65536L * P_OFF[q];
    const __nv_bfloat16* __restrict__ Wh = g_Wh + 4096L * P_OFF[q];
    const __nv_bfloat16* __restrict__ Wl = g_Wl + 4096L * P_OFF[q];

    if (tid < 64) lutS[tid] = g_lut[P_JB[q] + j0 + tid];

    // ldmatrix addresses at ks=0 (plane-relative); ks=1 -> ^32
    uint32_t addrA0[4], addrB0[2];
#pragma unroll
    for (int mf = 0; mf < 4; mf++) {
        int row = wm * 64 + mf * 16 + (lane & 15);
        addrA0[mf] = swz(row, (lane >> 4) & 1);
    }
#pragma unroll
    for (int nn = 0; nn < 2; nn++) {
        int row = wn * 32 + nn * 16 + ((lane >> 3) & 2) * 4 + (lane & 7);
        addrB0[nn] = swz(row, (lane >> 3) & 1);
    }

    float acc[4][4][4];
#pragma unroll
    for (int mf = 0; mf < 4; mf++)
#pragma unroll
        for (int ns = 0; ns < 4; ns++)
#pragma unroll
            for (int i = 0; i < 4; i++) acc[mf][ns][i] = 0.0f;

    const int rr = tid >> 2;     // 0..31
    const int cc = tid & 3;      // 16B chunk

    // prefetch chunk 0 into stage 0
    {
        uint32_t sb = sbase;
#pragma unroll
        for (int i = 0; i < 4; i++) {
            int r = rr + 32 * i;
            uint32_t so = swz(r, cc);
            long g = (long)(R0 + r) * Kl + cc * 8;
            cpasync16(sb + OFF_AH + so, Xh + g);
            cpasync16(sb + OFF_AL + so, Xl + g);
        }
#pragma unroll
        for (int i = 0; i < 2; i++) {
            int r = rr + 32 * i;
            uint32_t so = swz(r, cc);
            long g = (long)(j0 + r) * Kl + cc * 8;
            cpasync16(sb + OFF_BH + so, Wh + g);
            cpasync16(sb + OFF_BL + so, Wl + g);
        }
        CP_COMMIT();
    }

    for (int c = 0; c < nc; c++) {
        CP_WAIT0();
        __syncthreads();

        if (c + 1 < nc) {
            uint32_t sb = sbase + (uint32_t)(((c + 1) & 1) * ST);
            int k0 = (c + 1) * 32;
#pragma unroll
            for (int i = 0; i < 4; i++) {
                int r = rr + 32 * i;
                uint32_t so = swz(r, cc);
                long g = (long)(R0 + r) * Kl + k0 + cc * 8;
                cpasync16(sb + OFF_AH + so, Xh + g);
                cpasync16(sb + OFF_AL + so, Xl + g);
            }
#pragma unroll
            for (int i = 0; i < 2; i++) {
                int r = rr + 32 * i;
                uint32_t so = swz(r, cc);
                long g = (long)(j0 + r) * Kl + k0 + cc * 8;
                cpasync16(sb + OFF_BH + so, Wh + g);
                cpasync16(sb + OFF_BL + so, Wl + g);
            }
            CP_COMMIT();
        }

        const uint32_t sb = sbase + (uint32_t)((c & 1) * ST);
#pragma unroll
        for (int ks = 0; ks < 2; ks++) {
            const uint32_t kx = (uint32_t)(ks * 32);   // XOR, not add
            uint32_t a[4][4], bh[2][4], bl[2][4];
#pragma unroll
            for (int mf = 0; mf < 4; mf++) ldsm_x4(a[mf], sb + OFF_AH + (addrA0[mf] ^ kx));
#pragma unroll
            for (int nn = 0; nn < 2; nn++) ldsm_x4(bh[nn], sb + OFF_BH + (addrB0[nn] ^ kx));
#pragma unroll
            for (int nn = 0; nn < 2; nn++) ldsm_x4(bl[nn], sb + OFF_BL + (addrB0[nn] ^ kx));

            // hh + hl
#pragma unroll
            for (int mf = 0; mf < 4; mf++)
#pragma unroll
                for (int ns = 0; ns < 4; ns++) {
                    mma16816(acc[mf][ns], a[mf], &bh[ns >> 1][(ns & 1) * 2]);
                    mma16816(acc[mf][ns], a[mf], &bl[ns >> 1][(ns & 1) * 2]);
                }
            // lh
#pragma unroll
            for (int mf = 0; mf < 4; mf++) ldsm_x4(a[mf], sb + OFF_AL + (addrA0[mf] ^ kx));
#pragma unroll
            for (int mf = 0; mf < 4; mf++)
#pragma unroll
                for (int ns = 0; ns < 4; ns++)
                    mma16816(acc[mf][ns], a[mf], &bh[ns >> 1][(ns & 1) * 2]);
        }
        __syncthreads();
    }

    // ---- epilogue: scatter via LUT ----
#pragma unroll
    for (int mf = 0; mf < 4; mf++) {
        int row0 = R0 + wm * 64 + mf * 16 + (lane >> 2);
        int row1 = row0 + 8;
        int b0 = row0 / d, m0 = row0 - b0 * d;
        int b1 = row1 / d, m1 = row1 - b1 * d;
        long ob0 = (long)b0 * 29120 + m0;
        long ob1 = (long)b1 * 29120 + m1;
#pragma unroll
        for (int ns = 0; ns < 4; ns++) {
            int j = wn * 32 + ns * 8 + (lane & 3) * 2;
            int o0 = lutS[j], o1 = lutS[j + 1];
            out[ob0 + o0] = acc[mf][ns][0];
            out[ob0 + o1] = acc[mf][ns][1];
            out[ob1 + o0] = acc[mf][ns][2];
            out[ob1 + o1] = acc[mf][ns][3];
        }
    }
}

// ---------------------------------------------------------------------------
extern "C" void kernel_launch(void* const* d_in, const int* in_sizes, int n_in,
                              void* d_out, int out_size) {
    const float* x  = (const float*)d_in[0];
    const float* Dm = (const float*)d_in[1];
    const float* w  = (const float*)d_in[2];
    float* out = (float*)d_out;

    cudaFuncSetAttribute(prepare_kernel, cudaFuncAttributeMaxDynamicSharedMemorySize, 46912);
    cudaFuncSetAttribute(gemm_kernel, cudaFuncAttributeMaxDynamicSharedMemorySize, SM_TOT);

    prepare_kernel<<<7687, 256, 46912>>>(x, Dm, w);
    gemm_kernel<<<3640, 128, SM_TOT>>>(out);
}